// round 2
// baseline (speedup 1.0000x reference)
#include <cuda_runtime.h>

// Janossy pooling, k=2, n=2048, d=32 — single fused kernel.
//
// With rows sorted (stably) by X[:,0], sorted-position r appears first in
// (n-1-r) pairs and second in r pairs, so:
//   out[0][d] = sum_i X[i][d] * (n-1-r_i) / C(n,2)
//   out[1][d] = sum_i X[i][d] * r_i       / C(n,2)
// r_i = #{ j : X[j][0] < X[i][0]  or  (X[j][0] == X[i][0] and j < i) }.

#define NROWS 2048
#define NDIM  32
#define BLOCK 512               // 16 warps -> 16 rows per block
#define GRID  (NROWS / 16)      // 128 blocks, one wave

__device__ float        g_acc[2 * NDIM];   // zero-initialized; reset each run
__device__ unsigned int g_count;           // ticket counter; reset each run

__global__ __launch_bounds__(BLOCK) void janossy_fused(const float* __restrict__ X,
                                                       float* __restrict__ out) {
    __shared__ float skeys[NROWS];
    __shared__ float sacc[2 * NDIM];
    __shared__ int   s_last;

    const int tid  = threadIdx.x;
    const int warp = tid >> 5;
    const int lane = tid & 31;
    const int row  = blockIdx.x * 16 + warp;

    // Issue this warp's row read early (independent of staging).
    const float x = X[row * NDIM + lane];        // coalesced 128B row read

    // Stage all 2048 keys (strided gather from X column 0; L2-resident after
    // the first touches — total traffic across the grid is ~1 MB).
    #pragma unroll
    for (int t = tid; t < NROWS; t += BLOCK) skeys[t] = X[t * NDIM];
    if (tid < 2 * NDIM) sacc[tid] = 0.0f;
    __syncthreads();

    const float xi = skeys[row];                 // broadcast read

    // Rank via all-pairs count; float4 LDS (conflict-free: 8 thr x 16B / phase).
    int cnt = 0;
    const float4* sk4 = reinterpret_cast<const float4*>(skeys);
    #pragma unroll
    for (int m = 0; m < NROWS / 128; m++) {      // 16 iterations
        const int   q  = lane + m * 32;          // float4 index
        const float4 kv = sk4[q];
        const int   jb = q * 4;
        cnt += (int)(kv.x < xi) | ((int)(kv.x == xi) & (int)(jb + 0 < row));
        cnt += (int)(kv.y < xi) | ((int)(kv.y == xi) & (int)(jb + 1 < row));
        cnt += (int)(kv.z < xi) | ((int)(kv.z == xi) & (int)(jb + 2 < row));
        cnt += (int)(kv.w < xi) | ((int)(kv.w == xi) & (int)(jb + 3 < row));
    }
    const int r = __reduce_add_sync(0xffffffffu, cnt);

    // Weighted contribution; lane == feature dim.
    const float invC = 1.0f / 2096128.0f;        // 1 / C(2048,2)
    const float w0 = (float)(NROWS - 1 - r) * invC;
    const float w1 = (float)r * invC;
    atomicAdd(&sacc[lane],        x * w0);
    atomicAdd(&sacc[NDIM + lane], x * w1);
    __syncthreads();

    // Block partial -> global scratch, then last-block finalize.
    if (tid < 2 * NDIM) atomicAdd(&g_acc[tid], sacc[tid]);
    __threadfence();
    __syncthreads();
    if (tid == 0)
        s_last = (atomicAdd(&g_count, 1u) == (unsigned)(GRID - 1));
    __syncthreads();

    if (s_last) {
        __threadfence();                          // acquire: see all g_acc adds
        if (tid < 2 * NDIM) {
            out[tid]   = __ldcg(&g_acc[tid]);     // L2 read (bypass L1)
            g_acc[tid] = 0.0f;                    // reset for next replay
        }
        if (tid == 0) g_count = 0u;
    }
}

extern "C" void kernel_launch(void* const* d_in, const int* in_sizes, int n_in,
                              void* d_out, int out_size) {
    const float* X = (const float*)d_in[0];
    janossy_fused<<<GRID, BLOCK>>>(X, (float*)d_out);
}

// round 3
// speedup vs baseline: 1.0061x; 1.0061x over previous
#include <cuda_runtime.h>

// Janossy pooling, k=2, n=2048, d=32 — single launch, in-kernel global sync.
//
//   out[0][d] = sum_i X[i][d] * (n-1-r_i) / C(n,2)
//   out[1][d] = sum_i X[i][d] * r_i       / C(n,2)
// r_i = stable rank of X[i][0] (ties by original index, = jnp.argsort).
//
// Phase A: each block publishes its 16-key slice of column 0 into dense
//          g_keys (16 strided loads only — cheap).
// Sync:    release(fence) + monotone ticket; tid0 spins with acquire loads
//          until all 128 blocks of this replay have published. Safe: 128
//          blocks < 148 SMs, 1 block/SM -> all co-resident in one wave.
//          Counters are monotone (epoch arithmetic), so graph replays need
//          no reset and the kernel is deterministic.
// Phase B: stage dense keys (coalesced, L2-hit), warp-per-row rank count,
//          weighted accumulate, last-finisher writes out and re-zeros g_acc.

#define NROWS 2048
#define NDIM  32
#define BLOCK 512               // 16 warps -> 16 rows per block
#define GRID  (NROWS / 16)      // 128 blocks, one wave (< 148 SMs)

__device__ float        g_keys[NROWS];
__device__ float        g_acc[2 * NDIM];   // zero at start of every replay
__device__ unsigned int g_ready;           // monotone publish counter
__device__ unsigned int g_done;            // monotone finish counter

__global__ __launch_bounds__(BLOCK) void janossy_one(const float* __restrict__ X,
                                                     float* __restrict__ out) {
    __shared__ float skeys[NROWS];
    __shared__ float sacc[2 * NDIM];
    __shared__ int   s_last;

    const int tid  = threadIdx.x;
    const int warp = tid >> 5;
    const int lane = tid & 31;
    const int row  = blockIdx.x * 16 + warp;

    // Row read issued early (independent of everything below).
    const float x = X[row * NDIM + lane];          // coalesced 128B

    // ---- Phase A: publish this block's 16-key slice (16 wavefronts only).
    if (tid < 16) {
        const int t = blockIdx.x * 16 + tid;
        g_keys[t] = X[t * NDIM];
    }
    if (tid < 2 * NDIM) sacc[tid] = 0.0f;
    __threadfence();                               // release keys (writers fenced)
    __syncthreads();

    // ---- Device-wide sync: monotone epoch ticket, tid0 spins.
    if (tid == 0) {
        const unsigned my     = atomicAdd(&g_ready, 1u);
        const unsigned target = (my / GRID + 1u) * GRID;
        unsigned v;
        do {
            asm volatile("ld.acquire.gpu.u32 %0, [%1];" : "=r"(v) : "l"(&g_ready));
        } while (v < target);
    }
    __syncthreads();

    // ---- Phase B: stage dense keys (coalesced, 64 lines, L2-hit).
    #pragma unroll
    for (int t = tid; t < NROWS; t += BLOCK) skeys[t] = __ldcg(&g_keys[t]);
    __syncthreads();

    const float xi = skeys[row];

    // Rank via all-pairs count, float4 LDS (conflict-free), fully unrolled.
    int cnt = 0;
    const float4* sk4 = reinterpret_cast<const float4*>(skeys);
    #pragma unroll
    for (int m = 0; m < NROWS / 128; m++) {        // 16 iterations
        const int    q  = lane + m * 32;
        const float4 kv = sk4[q];
        const int    jb = q * 4;
        cnt += (int)(kv.x < xi) | ((int)(kv.x == xi) & (int)(jb + 0 < row));
        cnt += (int)(kv.y < xi) | ((int)(kv.y == xi) & (int)(jb + 1 < row));
        cnt += (int)(kv.z < xi) | ((int)(kv.z == xi) & (int)(jb + 2 < row));
        cnt += (int)(kv.w < xi) | ((int)(kv.w == xi) & (int)(jb + 3 < row));
    }
    const int r = __reduce_add_sync(0xffffffffu, cnt);

    // Weighted contribution; lane == feature dim.
    const float invC = 1.0f / 2096128.0f;          // 1 / C(2048,2)
    const float w0 = (float)(NROWS - 1 - r) * invC;
    const float w1 = (float)r * invC;
    atomicAdd(&sacc[lane],        x * w0);
    atomicAdd(&sacc[NDIM + lane], x * w1);
    __syncthreads();

    // Block partial -> global scratch; last finisher of THIS replay finalizes.
    if (tid < 2 * NDIM) atomicAdd(&g_acc[tid], sacc[tid]);
    __threadfence();
    __syncthreads();
    if (tid == 0)
        s_last = ((atomicAdd(&g_done, 1u) % GRID) == (unsigned)(GRID - 1));
    __syncthreads();

    if (s_last) {
        __threadfence();                           // acquire all g_acc adds
        if (tid < 2 * NDIM) {
            out[tid]   = __ldcg(&g_acc[tid]);
            g_acc[tid] = 0.0f;                     // ready for next replay
        }
    }
}

extern "C" void kernel_launch(void* const* d_in, const int* in_sizes, int n_in,
                              void* d_out, int out_size) {
    const float* X = (const float*)d_in[0];
    janossy_one<<<GRID, BLOCK>>>(X, (float*)d_out);
}

// round 4
// speedup vs baseline: 1.0343x; 1.0280x over previous
#include <cuda_runtime.h>

// Janossy pooling, k=2, n=2048, d=32 — prep + main with PDL overlap.
//
//   out[0][d] = sum_i X[i][d] * (n-1-r_i) / C(n,2)
//   out[1][d] = sum_i X[i][d] * r_i       / C(n,2)
// r_i = stable rank of X[i][0] (ties by original index == jnp.argsort).
//
// prep : compact strided keys X[:,0] -> dense g_keys (one pass, spread over
//        8 blocks) and zero g_acc for this replay.
// main : launched with programmatic stream serialization (PDL) — blocks ramp
//        during prep, do independent work, then cudaGridDependencySynchronize()
//        before reading g_keys. Epilogue: block partials -> g_acc atomics;
//        last finisher (monotone ticket) writes d_out.

#define NROWS 2048
#define NDIM  32
#define BLOCK 512               // 16 warps -> 16 rows per block
#define GRID  (NROWS / 16)      // 128 blocks

__device__ float        g_keys[NROWS];
__device__ float        g_acc[2 * NDIM];
__device__ unsigned int g_done;            // monotone across graph replays

__global__ void janossy_prep(const float* __restrict__ X) {
    const int t = blockIdx.x * blockDim.x + threadIdx.x;   // 8 x 256 = 2048
    g_keys[t] = X[t * NDIM];
    if (blockIdx.x == 0 && threadIdx.x < 2 * NDIM) g_acc[threadIdx.x] = 0.0f;
}

__global__ __launch_bounds__(BLOCK) void janossy_main(const float* __restrict__ X,
                                                      float* __restrict__ out) {
    __shared__ float skeys[NROWS];
    __shared__ float sacc[2 * NDIM];
    __shared__ int   s_last;

    const int tid  = threadIdx.x;
    const int warp = tid >> 5;
    const int lane = tid & 31;
    const int row  = blockIdx.x * 16 + warp;

    // Independent work before the grid dependency: row read + sacc init.
    const float x = X[row * NDIM + lane];          // coalesced 128B row
    if (tid < 2 * NDIM) sacc[tid] = 0.0f;

    // Wait for prep's writes (g_keys, g_acc) to be visible.
    cudaGridDependencySynchronize();

    // Stage dense keys: 64 coalesced lines, L2-hot (just written by prep).
    #pragma unroll
    for (int t = tid; t < NROWS; t += BLOCK) skeys[t] = g_keys[t];
    __syncthreads();

    const float xi = skeys[row];

    // Rank via all-pairs count; float4 LDS (conflict-free), fully unrolled.
    int cnt = 0;
    const float4* sk4 = reinterpret_cast<const float4*>(skeys);
    #pragma unroll
    for (int m = 0; m < NROWS / 128; m++) {        // 16 iterations
        const int    q  = lane + m * 32;
        const float4 kv = sk4[q];
        const int    jb = q * 4;
        cnt += (int)(kv.x < xi) | ((int)(kv.x == xi) & (int)(jb + 0 < row));
        cnt += (int)(kv.y < xi) | ((int)(kv.y == xi) & (int)(jb + 1 < row));
        cnt += (int)(kv.z < xi) | ((int)(kv.z == xi) & (int)(jb + 2 < row));
        cnt += (int)(kv.w < xi) | ((int)(kv.w == xi) & (int)(jb + 3 < row));
    }
    const int r = __reduce_add_sync(0xffffffffu, cnt);

    // Weighted contribution; lane == feature dim.
    const float invC = 1.0f / 2096128.0f;          // 1 / C(2048,2)
    const float w0 = (float)(NROWS - 1 - r) * invC;
    const float w1 = (float)r * invC;
    atomicAdd(&sacc[lane],        x * w0);
    atomicAdd(&sacc[NDIM + lane], x * w1);
    __syncthreads();

    // Block partial -> global scratch; last finisher of this replay writes out.
    if (tid < 2 * NDIM) atomicAdd(&g_acc[tid], sacc[tid]);
    __threadfence();
    __syncthreads();
    if (tid == 0)
        s_last = ((atomicAdd(&g_done, 1u) % GRID) == (unsigned)(GRID - 1));
    __syncthreads();

    if (s_last) {
        __threadfence();                           // acquire all g_acc adds
        if (tid < 2 * NDIM) out[tid] = g_acc[tid];
    }
}

extern "C" void kernel_launch(void* const* d_in, const int* in_sizes, int n_in,
                              void* d_out, int out_size) {
    const float* X = (const float*)d_in[0];
    float* out = (float*)d_out;

    janossy_prep<<<8, 256>>>(X);

    // Launch main with PDL: it may begin ramping while prep is still running;
    // cudaGridDependencySynchronize() inside gates the dependent reads.
    cudaLaunchConfig_t cfg = {};
    cfg.gridDim  = dim3(GRID, 1, 1);
    cfg.blockDim = dim3(BLOCK, 1, 1);
    cfg.dynamicSmemBytes = 0;
    cfg.stream = 0;                                 // same (legacy) stream
    cudaLaunchAttribute attr[1];
    attr[0].id = cudaLaunchAttributeProgrammaticStreamSerialization;
    attr[0].val.programmaticStreamSerializationAllowed = 1;
    cfg.attrs    = attr;
    cfg.numAttrs = 1;
    cudaLaunchKernelEx(&cfg, janossy_main, X, out);
}

// round 5
// speedup vs baseline: 1.0375x; 1.0031x over previous
#include <cuda_runtime.h>

// Janossy pooling, k=2, n=2048, d=32 — ONE kernel, tiled pair-sum.
//
// out[1][d] = (1/C) * sum_{i,j} [j ≺ i] * x_i[d]      (j≺i: key_j<key_i, ties j<i)
// out[0][d] = (1/C) * sum_{i,j} [i ≺ j] * x_i[d]
// Tiled over (i,j): block (itile,jtile) handles 128 i-rows x 256 j-keys.
// c_i  = #{j in J : j ≺ i}   (partial rank against this key slice)
// c'_i = 256 - c_i - [i in J] (pairs are exhaustive & exclusive; i==j in neither)
// Summing c_i (resp. c'_i) over all 8 jtiles gives exact r_i (resp. n-1-r_i).
// No block ever needs more than 256 strided key loads -> no full-key gather,
// no device-wide sync, no second kernel.

#define NROWS 2048
#define NDIM  32
#define BLOCK 512                // 16 warps x 8 rows = 128 rows per itile
#define ITILES 16
#define JTILES 8
#define JT     (NROWS / JTILES)  // 256 keys per j-slice
#define GRID   (ITILES * JTILES) // 128 blocks, one wave

__device__ float        g_acc[2 * NDIM];   // [0:32)=T0 (out0 sums), [32:64)=T1
__device__ unsigned int g_done;            // monotone ticket across replays

__global__ __launch_bounds__(BLOCK) void janossy_tiled(const float* __restrict__ X,
                                                       float* __restrict__ out) {
    __shared__ float skeys[JT];
    __shared__ float sacc[2 * NDIM];
    __shared__ int   s_last;

    const int tid   = threadIdx.x;
    const int warp  = tid >> 5;
    const int lane  = tid & 31;
    const int itile = blockIdx.x >> 3;     // 0..15
    const int jtile = blockIdx.x & 7;      // 0..7

    // Stage this block's 256-key slice (256 strided wavefronts only).
    if (tid < JT) skeys[tid] = X[(jtile * JT + tid) * NDIM];
    if (tid < 2 * NDIM) sacc[tid] = 0.0f;
    __syncthreads();

    const float4* sk4 = reinterpret_cast<const float4*>(skeys);

    float acc0 = 0.0f, acc1 = 0.0f;        // lane == feature dim
    const int rbase = itile * 128 + warp * 8;

    #pragma unroll
    for (int t = 0; t < 8; t++) {
        const int   i  = rbase + t;
        const float x  = X[i * NDIM + lane];                 // coalesced 128B
        const float xi = __shfl_sync(0xffffffffu, x, 0);     // key_i = x_i[0]

        // Count j ≺ i over this lane's 8 keys (2 conflict-free float4 LDS).
        int cnt = 0;
        #pragma unroll
        for (int m = 0; m < 2; m++) {
            const int    q  = lane + m * 32;
            const float4 kv = sk4[q];
            const int    jb = jtile * JT + q * 4;
            cnt += (int)(kv.x < xi) | ((int)(kv.x == xi) & (int)(jb + 0 < i));
            cnt += (int)(kv.y < xi) | ((int)(kv.y == xi) & (int)(jb + 1 < i));
            cnt += (int)(kv.z < xi) | ((int)(kv.z == xi) & (int)(jb + 2 < i));
            cnt += (int)(kv.w < xi) | ((int)(kv.w == xi) & (int)(jb + 3 < i));
        }
        const int c  = __reduce_add_sync(0xffffffffu, cnt);  // partial rank
        const int cp = JT - c - (int)((i >> 8) == jtile);    // i in J_jtile?

        acc1 += (float)c  * x;
        acc0 += (float)cp * x;
    }

    atomicAdd(&sacc[lane],        acc0);
    atomicAdd(&sacc[NDIM + lane], acc1);
    __syncthreads();

    // Block partial -> global scratch; last finisher of this replay writes out.
    if (tid < 2 * NDIM) atomicAdd(&g_acc[tid], sacc[tid]);
    __threadfence();
    __syncthreads();
    if (tid == 0)
        s_last = ((atomicAdd(&g_done, 1u) % GRID) == (unsigned)(GRID - 1));
    __syncthreads();

    if (s_last) {
        __threadfence();                          // acquire all g_acc adds
        const float invC = 1.0f / 2096128.0f;     // 1 / C(2048,2)
        if (tid < 2 * NDIM) {
            out[tid]   = g_acc[tid] * invC;
            g_acc[tid] = 0.0f;                    // ready for next replay
        }
    }
}

extern "C" void kernel_launch(void* const* d_in, const int* in_sizes, int n_in,
                              void* d_out, int out_size) {
    const float* X = (const float*)d_in[0];
    janossy_tiled<<<GRID, BLOCK>>>(X, (float*)d_out);
}

// round 6
// speedup vs baseline: 1.1731x; 1.1307x over previous
#include <cuda_runtime.h>

// Janossy pooling, k=2, n=2048, d=32 — ONE kernel, tiled pair-sum,
// leaderless fire-and-forget epilogue.
//
// out[1][d] = (1/C) sum_{i,j} [j ≺ i] x_i[d],  out[0][d] = (1/C) sum_{i,j} [i ≺ j] x_i[d]
// (j≺i: key_j<key_i, ties by index; exactly one of the two holds per pair).
// Block (itile,jtile): 128 i-rows x 256 j-keys; partial counts c / (256-c-[i∈J]).
//
// Zeroing protocol (replay-safe, monotone):
//   block 0 / warp 0: atomicExch out[0:64] = 0  -> syncwarp -> threadfence ->
//   g_zflag++ (monotone). Every block tickets g_start at entry; epoch = tick>>7.
//   Before the final RED.ADD into out, warp 0 acquire-polls g_zflag >= epoch+1
//   (already set by then -> one L2 read). Then 64 fire-and-forget REDG, exit.

#define NROWS 2048
#define NDIM  32
#define BLOCK 512                // 16 warps x 8 rows = 128 rows per itile
#define JT    256                // keys per j-slice
#define GRID  128                // 16 itiles x 8 jtiles, one wave

__device__ unsigned int g_start;   // monotone entry ticket
__device__ unsigned int g_zflag;   // monotone "out zeroed" epoch counter

__global__ __launch_bounds__(BLOCK) void janossy_ff(const float* __restrict__ X,
                                                    float* __restrict__ out) {
    __shared__ float    skeys[JT];
    __shared__ float    sacc[2 * NDIM];
    __shared__ unsigned s_tick;

    const int tid   = threadIdx.x;
    const int warp  = tid >> 5;
    const int lane  = tid & 31;
    const int itile = blockIdx.x >> 3;
    const int jtile = blockIdx.x & 7;

    // --- Block 0 / warp 0: zero out for this replay (overlapped with all work).
    if (blockIdx.x == 0 && warp == 0) {
        atomicExch(&out[lane], 0.0f);
        atomicExch(&out[lane + NDIM], 0.0f);
        __syncwarp();
        __threadfence();                       // release zeros before flag
        if (lane == 0) atomicAdd(&g_zflag, 1u);
    }

    // --- Entry ticket -> replay epoch (overlapped with staging).
    if (tid == 0) s_tick = atomicAdd(&g_start, 1u);

    // --- Stage this block's 256-key slice (strided; 16 same-jtile blocks share
    //     lines -> L2 hits for most). Preload this warp's 8 rows (MLP=8).
    if (tid < JT) skeys[tid] = X[(jtile * JT + tid) * NDIM];
    if (tid < 2 * NDIM) sacc[tid] = 0.0f;

    const int rbase = itile * 128 + warp * 8;
    float xr[8];
    #pragma unroll
    for (int t = 0; t < 8; t++) xr[t] = X[(rbase + t) * NDIM + lane];

    __syncthreads();
    const unsigned epoch = s_tick >> 7;        // tick / GRID

    const float4* sk4 = reinterpret_cast<const float4*>(skeys);
    float acc0 = 0.0f, acc1 = 0.0f;            // lane == feature dim

    #pragma unroll
    for (int t = 0; t < 8; t++) {
        const int   i  = rbase + t;
        const float x  = xr[t];
        const float xi = __shfl_sync(0xffffffffu, x, 0);   // key_i = x_i[0]

        int cnt = 0;
        #pragma unroll
        for (int m = 0; m < 2; m++) {
            const int    q  = lane + m * 32;
            const float4 kv = sk4[q];
            const int    jb = jtile * JT + q * 4;
            cnt += (int)(kv.x < xi) | ((int)(kv.x == xi) & (int)(jb + 0 < i));
            cnt += (int)(kv.y < xi) | ((int)(kv.y == xi) & (int)(jb + 1 < i));
            cnt += (int)(kv.z < xi) | ((int)(kv.z == xi) & (int)(jb + 2 < i));
            cnt += (int)(kv.w < xi) | ((int)(kv.w == xi) & (int)(jb + 3 < i));
        }
        const int c  = __reduce_add_sync(0xffffffffu, cnt);   // partial rank
        const int cp = JT - c - (int)((i >> 8) == jtile);     // i in this slice?

        acc1 += (float)c  * x;
        acc0 += (float)cp * x;
    }

    const float invC = 1.0f / 2096128.0f;      // fold 1/C into the partials
    atomicAdd(&sacc[lane],        acc0 * invC);
    atomicAdd(&sacc[NDIM + lane], acc1 * invC);
    __syncthreads();

    // --- Epilogue: warp 0 only. Acquire-poll the zero flag (expected already
    //     set -> single L2 read), then fire-and-forget RED.ADD into out.
    if (warp == 0) {
        unsigned v;
        do {
            asm volatile("ld.acquire.gpu.u32 %0, [%1];" : "=r"(v) : "l"(&g_zflag));
        } while (v < epoch + 1u);
        atomicAdd(&out[lane],        sacc[lane]);
        atomicAdd(&out[lane + NDIM], sacc[lane + NDIM]);
    }
}

extern "C" void kernel_launch(void* const* d_in, const int* in_sizes, int n_in,
                              void* d_out, int out_size) {
    const float* X = (const float*)d_in[0];
    janossy_ff<<<GRID, BLOCK>>>(X, (float*)d_out);
}